// round 3
// baseline (speedup 1.0000x reference)
#include <cuda_runtime.h>
#include <cuda_fp16.h>
#include <cstdint>

#define TOK 512
#define HD  4096
#define MDIM 11008

// ---------------- static scratch (allocation-free rule) ----------------
static __device__ __half g_xh[TOK * HD];        // x in fp16
static __device__ __half g_wg[MDIM * HD];       // dequant gate weights
static __device__ __half g_wu[MDIM * HD];       // dequant up weights
static __device__ __half g_wd[HD * MDIM];       // dequant down weights
static __device__ float  g_g [TOK * MDIM];      // gate GEMM output (fp32)
static __device__ __half g_h [TOK * MDIM];      // h = silu(g)*u (fp16)

__constant__ float c_nf4[16] = {
    -1.0f, -0.6961928009986877f, -0.5250730514526367f, -0.39491748809814453f,
    -0.28444138169288635f, -0.18477343022823334f, -0.09105003625154495f, 0.0f,
    0.07958029955625534f, 0.16093020141124725f, 0.24611230194568634f,
    0.33791524171829224f, 0.44070982933044434f, 0.5626170039176941f,
    0.7229568362236023f, 1.0f};

// ---------------- helpers ----------------
__device__ __forceinline__ void cp_async16(void* smem, const void* gmem) {
    uint32_t s = (uint32_t)__cvta_generic_to_shared(smem);
    asm volatile("cp.async.cg.shared.global [%0], [%1], 16;\n" :: "r"(s), "l"(gmem));
}
__device__ __forceinline__ void cp_commit() {
    asm volatile("cp.async.commit_group;\n" ::: "memory");
}
template <int N>
__device__ __forceinline__ void cp_wait() {
    asm volatile("cp.async.wait_group %0;\n" :: "n"(N) : "memory");
}
__device__ __forceinline__ void ldsm4(uint32_t (&r)[4], const __half* p) {
    uint32_t s = (uint32_t)__cvta_generic_to_shared((void*)p);
    asm volatile("ldmatrix.sync.aligned.m8n8.x4.shared.b16 {%0,%1,%2,%3}, [%4];\n"
                 : "=r"(r[0]), "=r"(r[1]), "=r"(r[2]), "=r"(r[3]) : "r"(s));
}
__device__ __forceinline__ void mma16816(float (&d)[4], const uint32_t (&a)[4],
                                         uint32_t b0, uint32_t b1) {
    asm volatile(
        "mma.sync.aligned.m16n8k16.row.col.f32.f16.f16.f32 "
        "{%0,%1,%2,%3},{%4,%5,%6,%7},{%8,%9},{%0,%1,%2,%3};\n"
        : "+f"(d[0]), "+f"(d[1]), "+f"(d[2]), "+f"(d[3])
        : "r"(a[0]), "r"(a[1]), "r"(a[2]), "r"(a[3]), "r"(b0), "r"(b1));
}
__device__ __forceinline__ float siluf(float v) {
    return v / (1.0f + __expf(-v));
}

// ---------------- kernel: x fp32 -> fp16 ----------------
__global__ void cvt_x_kernel(const float* __restrict__ x, __half* __restrict__ xh) {
    int i = blockIdx.x * blockDim.x + threadIdx.x;   // handles 4 elements
    float4 v = ((const float4*)x)[i];
    ((__half2*)xh)[2 * i]     = __floats2half2_rn(v.x, v.y);
    ((__half2*)xh)[2 * i + 1] = __floats2half2_rn(v.z, v.w);
}

// ---------------- kernel: NF4 dequant -> fp16 ----------------
// Each thread: 4 consecutive codes (one int4), same absmax block (64 | 4-aligned).
__global__ void dequant_nf4_kernel(const int* __restrict__ codes,
                                   const float* __restrict__ absmax,
                                   __half* __restrict__ out) {
    __shared__ float tab[16];
    if (threadIdx.x < 16) tab[threadIdx.x] = c_nf4[threadIdx.x];
    __syncthreads();
    int i = blockIdx.x * blockDim.x + threadIdx.x;
    int4 c = ((const int4*)codes)[i];
    float am = __ldg(&absmax[i >> 4]);               // (i*4)/64
    __half2 h0 = __floats2half2_rn(tab[c.x] * am, tab[c.y] * am);
    __half2 h1 = __floats2half2_rn(tab[c.z] * am, tab[c.w] * am);
    ((__half2*)out)[2 * i]     = h0;
    ((__half2*)out)[2 * i + 1] = h1;
}

// ---------------- GEMM: C[M=tok, N] = A[tok,K] * B[N,K]^T ----------------
// Block tile 128x128x32, 2-stage cp.async, 8 warps (2m x 4n), warp tile 64x32.
// EPI 0: store fp32 to Cf.  EPI 1: load G fp32, h = silu(G)*acc, store fp16 to H.
#define BM 128
#define BN 128
#define BK 32
#define LDS_W 40   // 32 + 8 halfs padding (80B row stride: 16B-aligned, conflict-free)

template <int EPI>
__global__ __launch_bounds__(256, 2)
void gemm_nf4(const __half* __restrict__ A, const __half* __restrict__ B,
              int K, int N, float* __restrict__ Cf,
              const float* __restrict__ G, __half* __restrict__ H) {
    __shared__ __half sA[2][BM * LDS_W];
    __shared__ __half sB[2][BN * LDS_W];

    const int tid  = threadIdx.x;
    const int lane = tid & 31;
    const int warp = tid >> 5;
    const int wm   = warp >> 2;     // 0..1
    const int wn   = warp & 3;      // 0..3
    const int bm   = blockIdx.x;    // token tile (fast dim -> L2 dedup of B)
    const int bn   = blockIdx.y;    // weight tile

    const size_t rowA0 = (size_t)bm * BM;
    const size_t rowB0 = (size_t)bn * BN;

    // tile loader: 256 threads x 2 chunks x 16B covers one 128x32 fp16 tile
    auto load_tile = [&](int st, int k0) {
#pragma unroll
        for (int i = 0; i < 2; ++i) {
            int ch = tid + i * 256;
            int r = ch >> 2, cc = (ch & 3) * 8;
            cp_async16(&sA[st][r * LDS_W + cc], A + (rowA0 + r) * K + k0 + cc);
        }
#pragma unroll
        for (int i = 0; i < 2; ++i) {
            int ch = tid + i * 256;
            int r = ch >> 2, cc = (ch & 3) * 8;
            cp_async16(&sB[st][r * LDS_W + cc], B + (rowB0 + r) * K + k0 + cc);
        }
    };

    float acc[4][4][4] = {};

    load_tile(0, 0);
    cp_commit();

    const int KT = K / BK;
    for (int kt = 0; kt < KT; ++kt) {
        int rs = kt & 1;
        if (kt + 1 < KT) {
            load_tile(rs ^ 1, (kt + 1) * BK);
            cp_commit();
            cp_wait<1>();
        } else {
            cp_wait<0>();
        }
        __syncthreads();

        const __half* a_s = sA[rs];
        const __half* b_s = sB[rs];
#pragma unroll
        for (int kk = 0; kk < 2; ++kk) {
            uint32_t af[4][4], bf[2][4];
            int arow = wm * 64 + (lane & 15);
            int acol = kk * 16 + (lane >> 4) * 8;
#pragma unroll
            for (int mi = 0; mi < 4; ++mi)
                ldsm4(af[mi], a_s + (arow + mi * 16) * LDS_W + acol);
            int brow = wn * 32 + (lane & 7) + ((lane >> 4) << 3);
            int bcol = kk * 16 + ((lane >> 3) & 1) * 8;
#pragma unroll
            for (int nb = 0; nb < 2; ++nb)
                ldsm4(bf[nb], b_s + (brow + nb * 16) * LDS_W + bcol);
#pragma unroll
            for (int mi = 0; mi < 4; ++mi)
#pragma unroll
                for (int ni = 0; ni < 4; ++ni)
                    mma16816(acc[mi][ni], af[mi],
                             bf[ni >> 1][(ni & 1) * 2], bf[ni >> 1][(ni & 1) * 2 + 1]);
        }
        __syncthreads();
    }

    // epilogue
    const int m0 = bm * BM + wm * 64;
    const int n0 = bn * BN + wn * 32;
#pragma unroll
    for (int mi = 0; mi < 4; ++mi) {
#pragma unroll
        for (int ni = 0; ni < 4; ++ni) {
            int r = m0 + mi * 16 + (lane >> 2);
            int c = n0 + ni * 8 + (lane & 3) * 2;
            float* p = acc[mi][ni];
            if (EPI == 0) {
                *(float2*)(Cf + (size_t)r * N + c)       = make_float2(p[0], p[1]);
                *(float2*)(Cf + (size_t)(r + 8) * N + c) = make_float2(p[2], p[3]);
            } else {
                float2 gv0 = *(const float2*)(G + (size_t)r * N + c);
                float2 gv1 = *(const float2*)(G + (size_t)(r + 8) * N + c);
                *(__half2*)(H + (size_t)r * N + c) =
                    __floats2half2_rn(siluf(gv0.x) * p[0], siluf(gv0.y) * p[1]);
                *(__half2*)(H + (size_t)(r + 8) * N + c) =
                    __floats2half2_rn(siluf(gv1.x) * p[2], siluf(gv1.y) * p[3]);
            }
        }
    }
}

// ---------------- launch ----------------
extern "C" void kernel_launch(void* const* d_in, const int* in_sizes, int n_in,
                              void* d_out, int out_size) {
    const float* x  = (const float*)d_in[0];
    const int*   gc = (const int*)d_in[1];
    const float* ga = (const float*)d_in[2];
    const int*   uc = (const int*)d_in[3];
    const float* ua = (const float*)d_in[4];
    const int*   dc = (const int*)d_in[5];
    const float* da = (const float*)d_in[6];
    float* out = (float*)d_out;

    __half *xh, *wg, *wu, *wd, *hh;
    float* gb;
    cudaGetSymbolAddress((void**)&xh, g_xh);
    cudaGetSymbolAddress((void**)&wg, g_wg);
    cudaGetSymbolAddress((void**)&wu, g_wu);
    cudaGetSymbolAddress((void**)&wd, g_wd);
    cudaGetSymbolAddress((void**)&gb, g_g);
    cudaGetSymbolAddress((void**)&hh, g_h);

    cvt_x_kernel<<<(TOK * HD / 4) / 256, 256>>>(x, xh);

    const int dq_blocks = (MDIM * HD / 4) / 256;   // 44032, exact
    dequant_nf4_kernel<<<dq_blocks, 256>>>(gc, ga, wg);
    dequant_nf4_kernel<<<dq_blocks, 256>>>(uc, ua, wu);
    dequant_nf4_kernel<<<dq_blocks, 256>>>(dc, da, wd);

    dim3 g12(TOK / BM, MDIM / BN);   // (4, 86)
    gemm_nf4<0><<<g12, 256>>>(xh, wg, HD, MDIM, gb, nullptr, nullptr);
    gemm_nf4<1><<<g12, 256>>>(xh, wu, HD, MDIM, nullptr, gb, hh);

    dim3 g3(TOK / BM, HD / BN);      // (4, 32)
    gemm_nf4<0><<<g3, 256>>>(hh, wd, MDIM, HD, out, nullptr, nullptr);
}